// round 5
// baseline (speedup 1.0000x reference)
#include <cuda_runtime.h>
#include <cuda_fp16.h>
#include <cstdint>

// out[b,o] = sum_{i,j} (x_a^j x_b^(8-j))[b,i] * (coeffs[o,i,j]*weights[o,i])
// GEMM: M=16384, N=256, K=2304 (=16 chunks of 144). HMMA m16n8k16 path.
// R5: removed the produce->mma barrier (double-buffer makes it redundant);
//     x loads batched for MLP; produce split in halves around mma slices.

#define BATCH   16384
#define IDIM    256
#define ODIM    256
#define CTAM    128
#define NCHUNK  16
#define PLANES  18
#define THREADS 256

#define A_PLANE 2064                        // 128 rows * 16B + 16B pad
#define A_STAGE (PLANES * A_PLANE)          // 37152
#define B_PLANE (ODIM * 16)                 // 4096
#define B_STAGE (PLANES * B_PLANE)          // 73728
#define SM_B    (2 * A_STAGE)               // 74304
#define SMEM_TOTAL (SM_B + 2 * B_STAGE)     // 221760

#define TWO_LOG2E 2.8853900817779268f

// Prefolded B operand: [chunk 16][plane 18][col 256][8 halves] = 1.18 MB
__device__ __align__(128) __half g_B[NCHUNK * PLANES * ODIM * 8];

__device__ __forceinline__ uint32_t s2u(const void* p) {
    return (uint32_t)__cvta_generic_to_shared(p);
}

// ---------------------------------------------------------------- prep kernel
__global__ void bern_prep(const float* __restrict__ weights,
                          const float* __restrict__ coeffs) {
    int gid = blockIdx.x * blockDim.x + threadIdx.x;   // 73728
    int o   = gid & 255;
    int idx = gid >> 8;
    int pl  = idx % PLANES;
    int c   = idx / PLANES;

    __half h[8];
    if (pl < 16) {
        int i = c * 16 + pl;
        float w = weights[o * IDIM + i];
        const float* cf = coeffs + (size_t)(o * IDIM + i) * 9;
#pragma unroll
        for (int j = 0; j < 8; j++) h[j] = __float2half_rn(cf[j] * w);
    } else {
#pragma unroll
        for (int off = 0; off < 8; off++) {
            int i = c * 16 + (pl - 16) * 8 + off;
            float w = weights[o * IDIM + i];
            h[off] = __float2half_rn(coeffs[((size_t)(o * IDIM + i)) * 9 + 8] * w);
        }
    }
    uint32_t u[4];
#pragma unroll
    for (int j = 0; j < 4; j++) {
        __half2 p = __halves2half2(h[2 * j], h[2 * j + 1]);
        u[j] = *reinterpret_cast<uint32_t*>(&p);
    }
    *reinterpret_cast<uint4*>(
        reinterpret_cast<char*>(g_B) + ((size_t)(c * PLANES + pl) * ODIM + o) * 16) =
        make_uint4(u[0], u[1], u[2], u[3]);
}

// ---------------------------------------------------------------- main kernel
__global__ void __launch_bounds__(THREADS, 1)
bern_gemm(const float* __restrict__ x, float* __restrict__ out) {
    extern __shared__ char smem[];
    const int tid  = threadIdx.x;
    const int wid  = tid >> 5;
    const int lane = tid & 31;
    const int mbase = blockIdx.x * CTAM;
    const int wm = wid & 1;        // 2 warps along M (64 rows each)
    const int wn = wid >> 1;       // 4 warps along N (64 cols each)

    float acc[4][8][4];
#pragma unroll
    for (int a = 0; a < 4; a++)
#pragma unroll
        for (int b = 0; b < 8; b++)
#pragma unroll
            for (int d = 0; d < 4; d++) acc[a][b][d] = 0.0f;

    // task geometry for produce: 4 tasks per half
    //   grp = wid*8 + r  ->  row = (grp&15)*8 + lane/4 ; ii = (grp>>4)*4 + lane%4
    const int prow = (lane >> 2);
    const int pii  = (lane & 3);

    // produce half h (r = h*4 .. h*4+3) of A chunk c into stage s
    auto produce_half = [&](int c, int s, int h) {
        const float* xp = x + (size_t)mbase * IDIM + c * 16;
        char* aS = smem + s * A_STAGE;
        float xv[4];
#pragma unroll
        for (int q = 0; q < 4; q++) {
            int grp = wid * 8 + h * 4 + q;
            int row = (grp & 15) * 8 + prow;
            int ii  = (grp >> 4) * 4 + pii;
            xv[q] = xp[row * IDIM + ii];
        }
#pragma unroll
        for (int q = 0; q < 4; q++) {
            int grp = wid * 8 + h * 4 + q;
            int row = (grp & 15) * 8 + prow;
            int ii  = (grp >> 4) * 4 + pii;
            float e  = exp2f(xv[q] * TWO_LOG2E);
            float t  = 1.0f - __fdividef(2.0f, e + 1.0f);
            float a = 1.0f + t, b = 1.0f - t;
            float ab = a * b, ab2 = ab * ab, ab3 = ab2 * ab, ab4 = ab2 * ab2;
            float a2 = a * a, b2 = b * b;
            float a4 = a2 * a2, b4 = b2 * b2;
            float a6 = a4 * a2, b6 = b4 * b2;
            float a8 = a4 * a4, b8 = b4 * b4;
            uint32_t u0, u1, u2, u3;
            { __half2 p = __floats2half2_rn(b8,       ab * b6);  u0 = *reinterpret_cast<uint32_t*>(&p); }
            { __half2 p = __floats2half2_rn(ab2 * b4, ab3 * b2); u1 = *reinterpret_cast<uint32_t*>(&p); }
            { __half2 p = __floats2half2_rn(ab4,      ab3 * a2); u2 = *reinterpret_cast<uint32_t*>(&p); }
            { __half2 p = __floats2half2_rn(ab2 * a4, ab * a6);  u3 = *reinterpret_cast<uint32_t*>(&p); }
            *reinterpret_cast<uint4*>(aS + ii * A_PLANE + row * 16) =
                make_uint4(u0, u1, u2, u3);
            *reinterpret_cast<__half*>(aS + (16 + (ii >> 3)) * A_PLANE + row * 16 +
                                       (ii & 7) * 2) = __float2half_rn(a8);
        }
    };

    auto loadB = [&](int c, int s) {
        const char* src = reinterpret_cast<const char*>(g_B) + (size_t)c * B_STAGE;
        char* dst = smem + SM_B + s * B_STAGE;
#pragma unroll
        for (int r = 0; r < B_STAGE / 16 / THREADS; r++) {   // 18
            int idx = (r * THREADS + tid) * 16;
            asm volatile("cp.async.cg.shared.global [%0], [%1], 16;"
                         :: "r"(s2u(dst + idx)), "l"(src + idx) : "memory");
        }
        asm volatile("cp.async.commit_group;" ::: "memory");
    };

    // mma over slices [kk0, kk1) of stage s
    auto domma = [&](int s, int kk0, int kk1) {
        char* aS = smem + s * A_STAGE;
        char* bS = smem + SM_B + s * B_STAGE;
        const int arow = wm * 64 + (lane & 7) + ((lane >> 3) & 1) * 8;
        const int apl  = (lane >> 4);
        const int bcol = wn * 64 + (lane & 7) + ((lane >> 4) & 1) * 8;
        const int bpl  = (lane >> 3) & 1;
#pragma unroll
        for (int kk = kk0; kk < kk1; kk++) {
            uint32_t afr[4][4];
#pragma unroll
            for (int mt = 0; mt < 4; mt++) {
                uint32_t ad = s2u(aS + (kk * 2 + apl) * A_PLANE + (arow + mt * 16) * 16);
                asm volatile("ldmatrix.sync.aligned.m8n8.x4.shared.b16 {%0,%1,%2,%3}, [%4];"
                             : "=r"(afr[mt][0]), "=r"(afr[mt][1]),
                               "=r"(afr[mt][2]), "=r"(afr[mt][3]) : "r"(ad));
            }
            uint32_t bfr[4][4];
#pragma unroll
            for (int g = 0; g < 4; g++) {
                uint32_t bd = s2u(bS + (kk * 2 + bpl) * B_PLANE + (bcol + g * 16) * 16);
                asm volatile("ldmatrix.sync.aligned.m8n8.x4.shared.b16 {%0,%1,%2,%3}, [%4];"
                             : "=r"(bfr[g][0]), "=r"(bfr[g][1]),
                               "=r"(bfr[g][2]), "=r"(bfr[g][3]) : "r"(bd));
            }
#pragma unroll
            for (int mt = 0; mt < 4; mt++)
#pragma unroll
                for (int g = 0; g < 4; g++)
#pragma unroll
                    for (int sub = 0; sub < 2; sub++) {
                        float* d = acc[mt][g * 2 + sub];
                        asm volatile(
                            "mma.sync.aligned.m16n8k16.row.col.f32.f16.f16.f32 "
                            "{%0,%1,%2,%3}, {%4,%5,%6,%7}, {%8,%9}, {%0,%1,%2,%3};"
                            : "+f"(d[0]), "+f"(d[1]), "+f"(d[2]), "+f"(d[3])
                            : "r"(afr[mt][0]), "r"(afr[mt][1]),
                              "r"(afr[mt][2]), "r"(afr[mt][3]),
                              "r"(bfr[g][sub * 2]), "r"(bfr[g][sub * 2 + 1]));
                    }
        }
    };

    // ---- pipeline: ONE sync per chunk; produce(c+1) overlaps domma(c)
    loadB(0, 0);
    produce_half(0, 0, 0);
    produce_half(0, 0, 1);
    __syncthreads();
    for (int c = 0; c < NCHUNK; c++) {
        int s = c & 1;
        if (c + 1 < NCHUNK) {
            loadB(c + 1, s ^ 1);
            asm volatile("cp.async.wait_group 1;" ::: "memory");
            produce_half(c + 1, s ^ 1, 0);
            domma(s, 0, 4);
            produce_half(c + 1, s ^ 1, 1);
            domma(s, 4, 9);
        } else {
            asm volatile("cp.async.wait_group 0;" ::: "memory");
            domma(s, 0, 9);
        }
        __syncthreads();
    }

    // ---- epilogue
#pragma unroll
    for (int mt = 0; mt < 4; mt++) {
        int row0 = mbase + wm * 64 + mt * 16 + (lane >> 2);
#pragma unroll
        for (int nf = 0; nf < 8; nf++) {
            int col = wn * 64 + nf * 8 + (lane & 3) * 2;
            *reinterpret_cast<float2*>(out + (size_t)row0 * ODIM + col) =
                make_float2(acc[mt][nf][0], acc[mt][nf][1]);
            *reinterpret_cast<float2*>(out + (size_t)(row0 + 8) * ODIM + col) =
                make_float2(acc[mt][nf][2], acc[mt][nf][3]);
        }
    }
}

// ---------------------------------------------------------------- launch
extern "C" void kernel_launch(void* const* d_in, const int* in_sizes, int n_in,
                              void* d_out, int out_size) {
    const float* x       = (const float*)d_in[0];  // [16384, 256]
    const float* weights = (const float*)d_in[1];  // [256, 256]
    const float* coeffs  = (const float*)d_in[2];  // [256, 256, 9]
    float* out = (float*)d_out;                    // [16384, 256] fp32

    cudaFuncSetAttribute(bern_gemm, cudaFuncAttributeMaxDynamicSharedMemorySize,
                         SMEM_TOTAL);

    bern_prep<<<(NCHUNK * PLANES * ODIM) / THREADS, THREADS>>>(weights, coeffs);
    bern_gemm<<<BATCH / CTAM, THREADS, SMEM_TOTAL>>>(x, out);
}

// round 6
// speedup vs baseline: 1.1022x; 1.1022x over previous
#include <cuda_runtime.h>
#include <cuda_fp16.h>
#include <cstdint>

// out[b,o] = sum_{i,j} (x_a^j x_b^(8-j))[b,i] * (coeffs[o,i,j]*weights[o,i])
// GEMM: M=16384, N=256, K=2304 (=16 chunks of 144). HMMA m16n8k16 path.
// R6: x loads for chunk c+1 prefetched into registers before domma(c) so the
//     DRAM latency is hidden under ~5 mma slices; produce is stall-free.

#define BATCH   16384
#define IDIM    256
#define ODIM    256
#define CTAM    128
#define NCHUNK  16
#define PLANES  18
#define THREADS 256

#define A_PLANE 2064                        // 128 rows * 16B + 16B pad
#define A_STAGE (PLANES * A_PLANE)          // 37152
#define B_PLANE (ODIM * 16)                 // 4096
#define B_STAGE (PLANES * B_PLANE)          // 73728
#define SM_B    (2 * A_STAGE)               // 74304
#define SMEM_TOTAL (SM_B + 2 * B_STAGE)     // 221760

#define TWO_LOG2E 2.8853900817779268f

// Prefolded B operand: [chunk 16][plane 18][col 256][8 halves] = 1.18 MB
__device__ __align__(128) __half g_B[NCHUNK * PLANES * ODIM * 8];

__device__ __forceinline__ uint32_t s2u(const void* p) {
    return (uint32_t)__cvta_generic_to_shared(p);
}

// ---------------------------------------------------------------- prep kernel
__global__ void bern_prep(const float* __restrict__ weights,
                          const float* __restrict__ coeffs) {
    int gid = blockIdx.x * blockDim.x + threadIdx.x;   // 73728
    int o   = gid & 255;
    int idx = gid >> 8;
    int pl  = idx % PLANES;
    int c   = idx / PLANES;

    __half h[8];
    if (pl < 16) {
        int i = c * 16 + pl;
        float w = weights[o * IDIM + i];
        const float* cf = coeffs + (size_t)(o * IDIM + i) * 9;
#pragma unroll
        for (int j = 0; j < 8; j++) h[j] = __float2half_rn(cf[j] * w);
    } else {
#pragma unroll
        for (int off = 0; off < 8; off++) {
            int i = c * 16 + (pl - 16) * 8 + off;
            float w = weights[o * IDIM + i];
            h[off] = __float2half_rn(coeffs[((size_t)(o * IDIM + i)) * 9 + 8] * w);
        }
    }
    uint32_t u[4];
#pragma unroll
    for (int j = 0; j < 4; j++) {
        __half2 p = __halves2half2(h[2 * j], h[2 * j + 1]);
        u[j] = *reinterpret_cast<uint32_t*>(&p);
    }
    *reinterpret_cast<uint4*>(
        reinterpret_cast<char*>(g_B) + ((size_t)(c * PLANES + pl) * ODIM + o) * 16) =
        make_uint4(u[0], u[1], u[2], u[3]);
}

// ---------------------------------------------------------------- main kernel
__global__ void __launch_bounds__(THREADS, 1)
bern_gemm(const float* __restrict__ x, float* __restrict__ out) {
    extern __shared__ char smem[];
    const int tid  = threadIdx.x;
    const int wid  = tid >> 5;
    const int lane = tid & 31;
    const int mbase = blockIdx.x * CTAM;
    const int wm = wid & 1;        // 2 warps along M (64 rows each)
    const int wn = wid >> 1;       // 4 warps along N (64 cols each)

    float acc[4][8][4];
#pragma unroll
    for (int a = 0; a < 4; a++)
#pragma unroll
        for (int b = 0; b < 8; b++)
#pragma unroll
            for (int d = 0; d < 4; d++) acc[a][b][d] = 0.0f;

    const int prow = (lane >> 2);
    const int pii  = (lane & 3);

    // ---- issue the 8 x-loads for chunk c (no consumption -> LDGs in flight)
    auto load_x = [&](int c, float* xv) {
        const float* xp = x + (size_t)mbase * IDIM + c * 16;
#pragma unroll
        for (int q = 0; q < 8; q++) {
            int grp = wid * 8 + q;
            int row = (grp & 15) * 8 + prow;
            int ii  = (grp >> 4) * 4 + pii;
            xv[q] = xp[row * IDIM + ii];
        }
    };

    // ---- produce A chunk into stage s from prefetched x values
    auto produce = [&](int s, const float* xv) {
        char* aS = smem + s * A_STAGE;
#pragma unroll
        for (int q = 0; q < 8; q++) {
            int grp = wid * 8 + q;
            int row = (grp & 15) * 8 + prow;
            int ii  = (grp >> 4) * 4 + pii;
            float e  = exp2f(xv[q] * TWO_LOG2E);
            float t  = 1.0f - __fdividef(2.0f, e + 1.0f);
            float a = 1.0f + t, b = 1.0f - t;
            float ab = a * b, ab2 = ab * ab, ab3 = ab2 * ab, ab4 = ab2 * ab2;
            float a2 = a * a, b2 = b * b;
            float a4 = a2 * a2, b4 = b2 * b2;
            float a6 = a4 * a2, b6 = b4 * b2;
            float a8 = a4 * a4, b8 = b4 * b4;
            uint32_t u0, u1, u2, u3;
            { __half2 p = __floats2half2_rn(b8,       ab * b6);  u0 = *reinterpret_cast<uint32_t*>(&p); }
            { __half2 p = __floats2half2_rn(ab2 * b4, ab3 * b2); u1 = *reinterpret_cast<uint32_t*>(&p); }
            { __half2 p = __floats2half2_rn(ab4,      ab3 * a2); u2 = *reinterpret_cast<uint32_t*>(&p); }
            { __half2 p = __floats2half2_rn(ab2 * a4, ab * a6);  u3 = *reinterpret_cast<uint32_t*>(&p); }
            *reinterpret_cast<uint4*>(aS + ii * A_PLANE + row * 16) =
                make_uint4(u0, u1, u2, u3);
            *reinterpret_cast<__half*>(aS + (16 + (ii >> 3)) * A_PLANE + row * 16 +
                                       (ii & 7) * 2) = __float2half_rn(a8);
        }
    };

    auto loadB = [&](int c, int s) {
        const char* src = reinterpret_cast<const char*>(g_B) + (size_t)c * B_STAGE;
        char* dst = smem + SM_B + s * B_STAGE;
#pragma unroll
        for (int r = 0; r < B_STAGE / 16 / THREADS; r++) {   // 18
            int idx = (r * THREADS + tid) * 16;
            asm volatile("cp.async.cg.shared.global [%0], [%1], 16;"
                         :: "r"(s2u(dst + idx)), "l"(src + idx) : "memory");
        }
        asm volatile("cp.async.commit_group;" ::: "memory");
    };

    // ---- mma over slices [kk0, kk1) of stage s
    auto domma = [&](int s, int kk0, int kk1) {
        char* aS = smem + s * A_STAGE;
        char* bS = smem + SM_B + s * B_STAGE;
        const int arow = wm * 64 + (lane & 7) + ((lane >> 3) & 1) * 8;
        const int apl  = (lane >> 4);
        const int bcol = wn * 64 + (lane & 7) + ((lane >> 4) & 1) * 8;
        const int bpl  = (lane >> 3) & 1;
#pragma unroll
        for (int kk = kk0; kk < kk1; kk++) {
            uint32_t afr[4][4];
#pragma unroll
            for (int mt = 0; mt < 4; mt++) {
                uint32_t ad = s2u(aS + (kk * 2 + apl) * A_PLANE + (arow + mt * 16) * 16);
                asm volatile("ldmatrix.sync.aligned.m8n8.x4.shared.b16 {%0,%1,%2,%3}, [%4];"
                             : "=r"(afr[mt][0]), "=r"(afr[mt][1]),
                               "=r"(afr[mt][2]), "=r"(afr[mt][3]) : "r"(ad));
            }
            uint32_t bfr[4][4];
#pragma unroll
            for (int g = 0; g < 4; g++) {
                uint32_t bd = s2u(bS + (kk * 2 + bpl) * B_PLANE + (bcol + g * 16) * 16);
                asm volatile("ldmatrix.sync.aligned.m8n8.x4.shared.b16 {%0,%1,%2,%3}, [%4];"
                             : "=r"(bfr[g][0]), "=r"(bfr[g][1]),
                               "=r"(bfr[g][2]), "=r"(bfr[g][3]) : "r"(bd));
            }
#pragma unroll
            for (int mt = 0; mt < 4; mt++)
#pragma unroll
                for (int g = 0; g < 4; g++)
#pragma unroll
                    for (int sub = 0; sub < 2; sub++) {
                        float* d = acc[mt][g * 2 + sub];
                        asm volatile(
                            "mma.sync.aligned.m16n8k16.row.col.f32.f16.f16.f32 "
                            "{%0,%1,%2,%3}, {%4,%5,%6,%7}, {%8,%9}, {%0,%1,%2,%3};"
                            : "+f"(d[0]), "+f"(d[1]), "+f"(d[2]), "+f"(d[3])
                            : "r"(afr[mt][0]), "r"(afr[mt][1]),
                              "r"(afr[mt][2]), "r"(afr[mt][3]),
                              "r"(bfr[g][sub * 2]), "r"(bfr[g][sub * 2 + 1]));
                    }
        }
    };

    // ---- pipeline: x LDGs for c+1 issued before domma(c); produce after 5 slices
    float xv[8], xn[8];
    load_x(0, xv);
    loadB(0, 0);
    produce(0, xv);
    __syncthreads();
    for (int c = 0; c < NCHUNK; c++) {
        int s = c & 1;
        if (c + 1 < NCHUNK) {
            load_x(c + 1, xn);                       // LDGs in flight
            loadB(c + 1, s ^ 1);
            asm volatile("cp.async.wait_group 1;" ::: "memory");
            domma(s, 0, 5);                          // ~1500+ cyc covers the LDGs
            produce(s ^ 1, xn);                      // stall-free consume
            domma(s, 5, 9);
        } else {
            asm volatile("cp.async.wait_group 0;" ::: "memory");
            domma(s, 0, 9);
        }
        __syncthreads();
    }

    // ---- epilogue
#pragma unroll
    for (int mt = 0; mt < 4; mt++) {
        int row0 = mbase + wm * 64 + mt * 16 + (lane >> 2);
#pragma unroll
        for (int nf = 0; nf < 8; nf++) {
            int col = wn * 64 + nf * 8 + (lane & 3) * 2;
            *reinterpret_cast<float2*>(out + (size_t)row0 * ODIM + col) =
                make_float2(acc[mt][nf][0], acc[mt][nf][1]);
            *reinterpret_cast<float2*>(out + (size_t)(row0 + 8) * ODIM + col) =
                make_float2(acc[mt][nf][2], acc[mt][nf][3]);
        }
    }
}

// ---------------------------------------------------------------- launch
extern "C" void kernel_launch(void* const* d_in, const int* in_sizes, int n_in,
                              void* d_out, int out_size) {
    const float* x       = (const float*)d_in[0];  // [16384, 256]
    const float* weights = (const float*)d_in[1];  // [256, 256]
    const float* coeffs  = (const float*)d_in[2];  // [256, 256, 9]
    float* out = (float*)d_out;                    // [16384, 256] fp32

    cudaFuncSetAttribute(bern_gemm, cudaFuncAttributeMaxDynamicSharedMemorySize,
                         SMEM_TOTAL);

    bern_prep<<<(NCHUNK * PLANES * ODIM) / THREADS, THREADS>>>(weights, coeffs);
    bern_gemm<<<BATCH / CTAM, THREADS, SMEM_TOTAL>>>(x, out);
}